// round 16
// baseline (speedup 1.0000x reference)
#include <cuda_runtime.h>
#include <cuda_fp16.h>
#include <math.h>
#include <stdint.h>

#define T_TOK   8192
#define DIM     1024
#define HID     4096
#define NEXP    8
#define TOPK    2

#define BM 128
#define BN 128
#define BK 64
#define STAGES 3
#define AP (BK + 8)                        // 72 fp16 per A row
#define BP (BN + 8)                        // 136 fp16 per B row
#define A_BYTES (BM * AP * 2)              // 18432
#define B_BYTES (BK * BP * 2)              // 17408
#define OFF_A 0
#define OFF_B (A_BYTES)
#define SSTRIDE (A_BYTES + B_BYTES)        // 35840
#define SM_HDR 1024
#define SMEM_TOTAL (SM_HDR + STAGES * SSTRIDE)   // 108544 -> 2 CTAs/SM

#define ROWS_MAX 17408

// -------- device scratch (NEVER passed as kernel arguments — symbol-shadow bug) --------
__device__ __half g_w1h[(size_t)NEXP * DIM * HID];
__device__ __half g_w2h[(size_t)NEXP * HID * DIM];
__device__ __half g_xh[(size_t)T_TOK * DIM];
__device__ __half g_hh[(size_t)ROWS_MAX * HID];
__device__ int   g_tok[ROWS_MAX];
__device__ float g_prow[ROWS_MAX];         // row -> gating prob
__device__ int   g_topk[T_TOK * TOPK];
__device__ float g_probs[T_TOK * TOPK];
__device__ int   g_cnt[NEXP];
__device__ float g_loadf[NEXP];
__device__ int   g_off[NEXP + 1];
__device__ int   g_cursor[NEXP];

// ---------------- helpers ----------------
__device__ __forceinline__ uint32_t smem_u32(const void* p) {
    uint32_t a;
    asm("{ .reg .u64 t; cvta.to.shared.u64 t, %1; cvt.u32.u64 %0, t; }" : "=r"(a) : "l"(p));
    return a;
}
__device__ __forceinline__ void cp16(uint32_t dst, const void* src) {
    asm volatile("cp.async.cg.shared.global [%0], [%1], 16;" :: "r"(dst), "l"(src));
}
__device__ __forceinline__ void cp16z(uint32_t dst, const void* src, int sz) {
    asm volatile("cp.async.cg.shared.global [%0], [%1], 16, %2;" :: "r"(dst), "l"(src), "r"(sz));
}
#define CP_COMMIT() asm volatile("cp.async.commit_group;" ::: "memory")
#define CP_WAIT1()  asm volatile("cp.async.wait_group 1;" ::: "memory")

__device__ __forceinline__ void ldm_x4(uint32_t* r, uint32_t addr) {
    asm volatile("ldmatrix.sync.aligned.m8n8.x4.shared.b16 {%0,%1,%2,%3}, [%4];"
                 : "=r"(r[0]), "=r"(r[1]), "=r"(r[2]), "=r"(r[3]) : "r"(addr));
}
__device__ __forceinline__ void ldm_x4_t(uint32_t* r, uint32_t addr) {
    asm volatile("ldmatrix.sync.aligned.m8n8.x4.trans.shared.b16 {%0,%1,%2,%3}, [%4];"
                 : "=r"(r[0]), "=r"(r[1]), "=r"(r[2]), "=r"(r[3]) : "r"(addr));
}
__device__ __forceinline__ void mma_f16(float* c, const uint32_t* a, const uint32_t* b) {
    asm volatile("mma.sync.aligned.m16n8k16.row.col.f32.f16.f16.f32 "
                 "{%0,%1,%2,%3}, {%4,%5,%6,%7}, {%8,%9}, {%0,%1,%2,%3};"
                 : "+f"(c[0]), "+f"(c[1]), "+f"(c[2]), "+f"(c[3])
                 : "r"(a[0]), "r"(a[1]), "r"(a[2]), "r"(a[3]), "r"(b[0]), "r"(b[1]));
}

// ---------------- small kernels ----------------
// zeroes row maps + counters + the combined-output region (2 atomic adds/elem later)
__global__ void init_kernel(float* __restrict__ out) {
    int i = blockIdx.x * blockDim.x + threadIdx.x;
    if (i < ROWS_MAX) { g_tok[i] = -1; g_prow[i] = 0.0f; }
    if (i < NEXP) { g_cnt[i] = 0; g_loadf[i] = 0.0f; }
    int n4 = T_TOK * DIM / 4;
    for (int j = i; j < n4; j += gridDim.x * blockDim.x)
        ((float4*)out)[j] = make_float4(0.f, 0.f, 0.f, 0.f);
}

// gate + fused x -> fp16 conversion (writes g_xh while x row is resident)
__global__ void gate_kernel(const float* __restrict__ x,
                            const float* __restrict__ gw,
                            const float* __restrict__ gb) {
    int gtid = blockIdx.x * blockDim.x + threadIdx.x;
    int t = gtid >> 5, lane = gtid & 31;
    if (t >= T_TOK) return;
    const float* xr = x + (size_t)t * DIM;
    __half* xh = g_xh + (size_t)t * DIM;
    float acc[NEXP];
#pragma unroll
    for (int e = 0; e < NEXP; e++) acc[e] = 0.0f;
    for (int i = lane; i < DIM; i += 32) {
        float xv = xr[i];
        xh[i] = __float2half_rn(xv);
        const float* g = gw + (size_t)i * NEXP;
#pragma unroll
        for (int e = 0; e < NEXP; e++) acc[e] = fmaf(xv, g[e], acc[e]);
    }
#pragma unroll
    for (int e = 0; e < NEXP; e++)
#pragma unroll
        for (int o = 16; o > 0; o >>= 1)
            acc[e] += __shfl_xor_sync(0xffffffffu, acc[e], o);
    if (lane == 0) {
        float l[NEXP];
#pragma unroll
        for (int e = 0; e < NEXP; e++) l[e] = acc[e] + gb[e];
        int i0 = 0;
#pragma unroll
        for (int e = 1; e < NEXP; e++) if (l[e] > l[i0]) i0 = e;
        int i1 = -1;
#pragma unroll
        for (int e = 0; e < NEXP; e++) {
            if (e == i0) continue;
            if (i1 < 0 || l[e] > l[i1]) i1 = e;
        }
        float e1 = expf(l[i1] - l[i0]);
        float s = 1.0f + e1;
        g_topk[2 * t] = i0;  g_topk[2 * t + 1] = i1;
        g_probs[2 * t] = 1.0f / s;  g_probs[2 * t + 1] = e1 / s;
        atomicAdd(&g_cnt[i0], 1);  atomicAdd(&g_cnt[i1], 1);
        atomicAdd(&g_loadf[i0], 1.0f / s);  atomicAdd(&g_loadf[i1], e1 / s);
    }
}

__global__ void finalize_gate_kernel(float* __restrict__ out, long long out_size) {
    if (threadIdx.x == 0 && blockIdx.x == 0) {
        int off = 0;
        for (int e = 0; e < NEXP; e++) {
            g_off[e] = off;  g_cursor[e] = off;
            off += ((g_cnt[e] + BM - 1) / BM) * BM;
        }
        g_off[NEXP] = off;
        if (out_size >= (long long)T_TOK * DIM + 1 + NEXP) {
            float* tail = out + (size_t)T_TOK * DIM;
            float loss = 0.0f;
            for (int e = 0; e < NEXP; e++) {
                float le = g_loadf[e] / (float)T_TOK;
                tail[1 + e] = le;
                float d = le - 1.0f / (float)NEXP;
                loss += d * d;
            }
            tail[0] = 0.01f * loss;
        }
    }
}

__global__ void scatter_kernel() {
    int i = blockIdx.x * blockDim.x + threadIdx.x;
    if (i >= T_TOK * TOPK) return;
    int e = g_topk[i];
    int r = atomicAdd(&g_cursor[e], 1);
    g_tok[r] = i >> 1;
    g_prow[r] = g_probs[i];
}

// weights only now: w1 -> g_w1h, w2 -> g_w2h (fp16 round)
#define W4  ((size_t)NEXP * DIM * HID / 4)
__global__ void split_w_kernel(const float* __restrict__ w1,
                               const float* __restrict__ w2) {
    size_t i = (size_t)blockIdx.x * blockDim.x + threadIdx.x;
    if (i >= 2 * W4) return;
    const float* src = (i < W4) ? w1 : w2;
    __half* dst = (i < W4) ? g_w1h : g_w2h;
    size_t k = (i < W4) ? i : i - W4;
    float4 v = ((const float4*)src)[k];
    uint2 ph;
    ph.x = ((uint32_t)__half_as_ushort(__float2half_rn(v.y)) << 16) | __half_as_ushort(__float2half_rn(v.x));
    ph.y = ((uint32_t)__half_as_ushort(__float2half_rn(v.w)) << 16) | __half_as_ushort(__float2half_rn(v.z));
    ((uint2*)dst)[k] = ph;
}

// ---------------- HMMA grouped GEMM (fp16 single-pass, BK=64, 3-stage, 2 CTA/SM) ----
// mode 1: g_hh = fp16(gelu(gather(x) @ W1[e] + b1[e]))
// mode 2: out[t] += p * (g_hh @ W2[e] + b2[e])   (fused combine; exactly 2 adds/elem)
__global__ void __launch_bounds__(256, 2)
moe_gemm_kernel(const float* __restrict__ bias, float* __restrict__ out,
                int K, int Ntot, int mode) {
    extern __shared__ __align__(1024) char smem[];
    int row0 = blockIdx.y * BM;
    if (row0 >= g_off[NEXP]) return;
    int col0 = blockIdx.x * BN;

    int tid = threadIdx.x;
    int wid = tid >> 5, lane = tid & 31;
    int wm = wid & 3, wn = wid >> 2;

    uint32_t sdata = smem_u32(smem) + SM_HDR;
    int* s_tok = (int*)smem;                 // 128 ints
    float* s_prob = (float*)(smem + 512);    // 128 floats

    int e = 0;
#pragma unroll
    for (int i = 0; i < NEXP; i++) if (row0 >= g_off[i + 1]) e++;

    if (tid < BM) {
        s_tok[tid] = g_tok[row0 + tid];
        if (mode == 2) s_prob[tid] = g_prow[row0 + tid];
    }
    __syncthreads();

    const __half* Wh = ((mode == 1) ? g_w1h : g_w2h) + (size_t)e * K * Ntot;

    const int NC = K / BK;

    auto issue = [&](int c) {
        if (c < NC) {
            uint32_t sb = sdata + (c % STAGES) * SSTRIDE;
            int k0 = c * BK;
            // A: 128 rows x 64 fp16 = 1024 chunks of 16B
#pragma unroll
            for (int i = 0; i < 4; i++) {
                int j = i * 256 + tid;
                int ar = j >> 3, ac = (j & 7) * 8;
                uint32_t dA = sb + OFF_A + (uint32_t)(ar * AP + ac) * 2;
                if (mode == 1) {
                    int tk = s_tok[ar];
                    int sz = (tk >= 0) ? 16 : 0;
                    size_t so = (size_t)(tk >= 0 ? tk : 0) * DIM + k0 + ac;
                    cp16z(dA, g_xh + so, sz);
                } else {
                    cp16(dA, g_hh + (size_t)(row0 + ar) * HID + k0 + ac);
                }
            }
            // B: 64 rows x 128 fp16 = 1024 chunks
#pragma unroll
            for (int i = 0; i < 4; i++) {
                int j = i * 256 + tid;
                int br = j >> 4, bc = (j & 15) * 8;
                uint32_t dB = sb + OFF_B + (uint32_t)(br * BP + bc) * 2;
                cp16(dB, Wh + (size_t)(k0 + br) * Ntot + col0 + bc);
            }
        }
        CP_COMMIT();
    };

    float acc[2][8][4];
#pragma unroll
    for (int mf = 0; mf < 2; mf++)
#pragma unroll
        for (int nf = 0; nf < 8; nf++)
#pragma unroll
            for (int q = 0; q < 4; q++) acc[mf][nf][q] = 0.0f;

    issue(0);
    issue(1);

    for (int c = 0; c < NC; c++) {
        CP_WAIT1();
        __syncthreads();
        // issue c+2 BEFORE compute: buffer (c+2)%3 == (c-1)%3, all reads of it
        // completed before the barrier above -> safe, and loads overlap compute(c)
        issue(c + 2);
        uint32_t sb = sdata + (c % STAGES) * SSTRIDE;

#pragma unroll
        for (int ks = 0; ks < 4; ks++) {
            uint32_t ah[2][4];
#pragma unroll
            for (int mf = 0; mf < 2; mf++) {
                uint32_t off = (uint32_t)((wm * 32 + mf * 16 + (lane & 15)) * AP
                                          + ks * 16 + (lane >> 4) * 8) * 2;
                ldm_x4(ah[mf], sb + OFF_A + off);
            }
            uint32_t bh[8][2];
#pragma unroll
            for (int ng = 0; ng < 4; ng++) {
                uint32_t off = (uint32_t)((ks * 16 + (lane & 15)) * BP
                                          + wn * 64 + ng * 16 + (lane >> 4) * 8) * 2;
                uint32_t r[4];
                ldm_x4_t(r, sb + OFF_B + off);
                bh[2 * ng][0] = r[0]; bh[2 * ng][1] = r[1];
                bh[2 * ng + 1][0] = r[2]; bh[2 * ng + 1][1] = r[3];
            }
#pragma unroll
            for (int mf = 0; mf < 2; mf++)
#pragma unroll
                for (int nf = 0; nf < 8; nf++)
                    mma_f16(acc[mf][nf], ah[mf], bh[nf]);
        }
    }

    // ---- epilogue ----
    int grow = lane >> 2;
    int gcol = (lane & 3) * 2;
    if (mode == 1) {
#pragma unroll
        for (int nf = 0; nf < 8; nf++) {
            int col = col0 + wn * 64 + nf * 8 + gcol;
            float b0 = bias[(size_t)e * Ntot + col];
            float b1 = bias[(size_t)e * Ntot + col + 1];
#pragma unroll
            for (int mf = 0; mf < 2; mf++) {
                int rb = row0 + wm * 32 + mf * 16 + grow;
#pragma unroll
                for (int h = 0; h < 2; h++) {
                    int r = rb + h * 8;
                    float v0 = acc[mf][nf][2 * h]     + b0;
                    float v1 = acc[mf][nf][2 * h + 1] + b1;
                    v0 = 0.5f * v0 * (1.0f + erff(v0 * 0.70710678118654752f));
                    v1 = 0.5f * v1 * (1.0f + erff(v1 * 0.70710678118654752f));
                    uint32_t ph = ((uint32_t)__half_as_ushort(__float2half_rn(v1)) << 16)
                                  | __half_as_ushort(__float2half_rn(v0));
                    *(uint32_t*)(g_hh + (size_t)r * HID + col) = ph;
                }
            }
        }
    } else {
        // fused combine: out[t, col] += p * (acc + b2[e, col]); two commutative adds/elem
#pragma unroll
        for (int nf = 0; nf < 8; nf++) {
            int col = col0 + wn * 64 + nf * 8 + gcol;
            float b0 = bias[(size_t)e * Ntot + col];
            float b1 = bias[(size_t)e * Ntot + col + 1];
#pragma unroll
            for (int mf = 0; mf < 2; mf++) {
                int rloc = wm * 32 + mf * 16 + grow;
#pragma unroll
                for (int h = 0; h < 2; h++) {
                    int rl = rloc + h * 8;
                    int t = s_tok[rl];
                    if (t >= 0) {
                        float p = s_prob[rl];
                        float* o = out + (size_t)t * DIM + col;
                        atomicAdd(o,     p * (acc[mf][nf][2 * h]     + b0));
                        atomicAdd(o + 1, p * (acc[mf][nf][2 * h + 1] + b1));
                    }
                }
            }
        }
    }
}

// ---------------- launch ----------------
extern "C" void kernel_launch(void* const* d_in, const int* in_sizes, int n_in,
                              void* d_out, int out_size) {
    const float* x      = (const float*)d_in[0];
    const float* gate_w = (const float*)d_in[1];
    const float* gate_b = (const float*)d_in[2];
    const float* w1     = (const float*)d_in[3];
    const float* b1     = (const float*)d_in[4];
    const float* w2     = (const float*)d_in[5];
    const float* b2     = (const float*)d_in[6];
    float* out = (float*)d_out;

    cudaFuncSetAttribute(moe_gemm_kernel,
                         cudaFuncAttributeMaxDynamicSharedMemorySize, SMEM_TOTAL);

    init_kernel<<<2048, 256>>>(out);
    gate_kernel<<<(T_TOK * 32) / 256, 256>>>(x, gate_w, gate_b);
    finalize_gate_kernel<<<1, 32>>>(out, (long long)out_size);
    scatter_kernel<<<(T_TOK * TOPK + 255) / 256, 256>>>();
    split_w_kernel<<<(unsigned)((2 * W4 + 255) / 256), 256>>>(w1, w2);
    // GEMM1: K=1024, N=4096
    {
        dim3 grid(HID / BN, ROWS_MAX / BM);
        moe_gemm_kernel<<<grid, 256, SMEM_TOTAL>>>(b1, out, DIM, HID, 1);
    }
    // GEMM2 (+fused combine): K=4096, N=1024
    {
        dim3 grid(DIM / BN, ROWS_MAX / BM);
        moe_gemm_kernel<<<grid, 256, SMEM_TOTAL>>>(b2, out, HID, DIM, 2);
    }
}

// round 17
// speedup vs baseline: 1.0228x; 1.0228x over previous
#include <cuda_runtime.h>
#include <cuda_fp16.h>
#include <math.h>
#include <stdint.h>

#define T_TOK   8192
#define DIM     1024
#define HID     4096
#define NEXP    8
#define TOPK    2

#define BM 128
#define BN 128
#define BK 64
#define STAGES 3
#define AP (BK + 8)                        // 72 fp16 per A row
#define BP (BN + 8)                        // 136 fp16 per B row
#define A_BYTES (BM * AP * 2)              // 18432
#define B_BYTES (BK * BP * 2)              // 17408
#define OFF_A 0
#define OFF_B (A_BYTES)
#define SSTRIDE (A_BYTES + B_BYTES)        // 35840
#define SM_HDR 1024
#define SMEM_TOTAL (SM_HDR + STAGES * SSTRIDE)   // 108544 -> 2 CTAs/SM

#define ROWS_MAX 17408

// -------- device scratch (NEVER passed as kernel arguments — symbol-shadow bug) --------
__device__ __half g_w1h[(size_t)NEXP * DIM * HID];
__device__ __half g_w2h[(size_t)NEXP * HID * DIM];
__device__ __half g_xh[(size_t)T_TOK * DIM];
__device__ __half g_hh[(size_t)ROWS_MAX * HID];
__device__ int   g_tok[ROWS_MAX];
__device__ float g_prow[ROWS_MAX];         // row -> gating prob
__device__ int   g_topk[T_TOK * TOPK];
__device__ float g_probs[T_TOK * TOPK];
__device__ int   g_cnt[NEXP];
__device__ float g_loadf[NEXP];
__device__ int   g_off[NEXP + 1];
__device__ int   g_cursor[NEXP];

// ---------------- helpers ----------------
__device__ __forceinline__ uint32_t smem_u32(const void* p) {
    uint32_t a;
    asm("{ .reg .u64 t; cvta.to.shared.u64 t, %1; cvt.u32.u64 %0, t; }" : "=r"(a) : "l"(p));
    return a;
}
__device__ __forceinline__ void cp16(uint32_t dst, const void* src) {
    asm volatile("cp.async.cg.shared.global [%0], [%1], 16;" :: "r"(dst), "l"(src));
}
__device__ __forceinline__ void cp16z(uint32_t dst, const void* src, int sz) {
    asm volatile("cp.async.cg.shared.global [%0], [%1], 16, %2;" :: "r"(dst), "l"(src), "r"(sz));
}
#define CP_COMMIT() asm volatile("cp.async.commit_group;" ::: "memory")
#define CP_WAIT1()  asm volatile("cp.async.wait_group 1;" ::: "memory")

__device__ __forceinline__ void ldm_x4(uint32_t* r, uint32_t addr) {
    asm volatile("ldmatrix.sync.aligned.m8n8.x4.shared.b16 {%0,%1,%2,%3}, [%4];"
                 : "=r"(r[0]), "=r"(r[1]), "=r"(r[2]), "=r"(r[3]) : "r"(addr));
}
__device__ __forceinline__ void ldm_x4_t(uint32_t* r, uint32_t addr) {
    asm volatile("ldmatrix.sync.aligned.m8n8.x4.trans.shared.b16 {%0,%1,%2,%3}, [%4];"
                 : "=r"(r[0]), "=r"(r[1]), "=r"(r[2]), "=r"(r[3]) : "r"(addr));
}
__device__ __forceinline__ void mma_f16(float* c, const uint32_t* a, const uint32_t* b) {
    asm volatile("mma.sync.aligned.m16n8k16.row.col.f32.f16.f16.f32 "
                 "{%0,%1,%2,%3}, {%4,%5,%6,%7}, {%8,%9}, {%0,%1,%2,%3};"
                 : "+f"(c[0]), "+f"(c[1]), "+f"(c[2]), "+f"(c[3])
                 : "r"(a[0]), "r"(a[1]), "r"(a[2]), "r"(a[3]), "r"(b[0]), "r"(b[1]));
}

// ---------------- small kernels ----------------
// zeroes row maps + counters + the combined-output region (2 atomic adds/elem later)
__global__ void init_kernel(float* __restrict__ out) {
    int i = blockIdx.x * blockDim.x + threadIdx.x;
    if (i < ROWS_MAX) { g_tok[i] = -1; g_prow[i] = 0.0f; }
    if (i < NEXP) { g_cnt[i] = 0; g_loadf[i] = 0.0f; }
    int n4 = T_TOK * DIM / 4;
    for (int j = i; j < n4; j += gridDim.x * blockDim.x)
        ((float4*)out)[j] = make_float4(0.f, 0.f, 0.f, 0.f);
}

// gate + fused x -> fp16 conversion (writes g_xh while x row is resident)
__global__ void gate_kernel(const float* __restrict__ x,
                            const float* __restrict__ gw,
                            const float* __restrict__ gb) {
    int gtid = blockIdx.x * blockDim.x + threadIdx.x;
    int t = gtid >> 5, lane = gtid & 31;
    if (t >= T_TOK) return;
    const float* xr = x + (size_t)t * DIM;
    __half* xh = g_xh + (size_t)t * DIM;
    float acc[NEXP];
#pragma unroll
    for (int e = 0; e < NEXP; e++) acc[e] = 0.0f;
    for (int i = lane; i < DIM; i += 32) {
        float xv = xr[i];
        xh[i] = __float2half_rn(xv);
        const float* g = gw + (size_t)i * NEXP;
#pragma unroll
        for (int e = 0; e < NEXP; e++) acc[e] = fmaf(xv, g[e], acc[e]);
    }
#pragma unroll
    for (int e = 0; e < NEXP; e++)
#pragma unroll
        for (int o = 16; o > 0; o >>= 1)
            acc[e] += __shfl_xor_sync(0xffffffffu, acc[e], o);
    if (lane == 0) {
        float l[NEXP];
#pragma unroll
        for (int e = 0; e < NEXP; e++) l[e] = acc[e] + gb[e];
        int i0 = 0;
#pragma unroll
        for (int e = 1; e < NEXP; e++) if (l[e] > l[i0]) i0 = e;
        int i1 = -1;
#pragma unroll
        for (int e = 0; e < NEXP; e++) {
            if (e == i0) continue;
            if (i1 < 0 || l[e] > l[i1]) i1 = e;
        }
        float e1 = expf(l[i1] - l[i0]);
        float s = 1.0f + e1;
        g_topk[2 * t] = i0;  g_topk[2 * t + 1] = i1;
        g_probs[2 * t] = 1.0f / s;  g_probs[2 * t + 1] = e1 / s;
        atomicAdd(&g_cnt[i0], 1);  atomicAdd(&g_cnt[i1], 1);
        atomicAdd(&g_loadf[i0], 1.0f / s);  atomicAdd(&g_loadf[i1], e1 / s);
    }
}

__global__ void finalize_gate_kernel(float* __restrict__ out, long long out_size) {
    if (threadIdx.x == 0 && blockIdx.x == 0) {
        int off = 0;
        for (int e = 0; e < NEXP; e++) {
            g_off[e] = off;  g_cursor[e] = off;
            off += ((g_cnt[e] + BM - 1) / BM) * BM;
        }
        g_off[NEXP] = off;
        if (out_size >= (long long)T_TOK * DIM + 1 + NEXP) {
            float* tail = out + (size_t)T_TOK * DIM;
            float loss = 0.0f;
            for (int e = 0; e < NEXP; e++) {
                float le = g_loadf[e] / (float)T_TOK;
                tail[1 + e] = le;
                float d = le - 1.0f / (float)NEXP;
                loss += d * d;
            }
            tail[0] = 0.01f * loss;
        }
    }
}

__global__ void scatter_kernel() {
    int i = blockIdx.x * blockDim.x + threadIdx.x;
    if (i >= T_TOK * TOPK) return;
    int e = g_topk[i];
    int r = atomicAdd(&g_cursor[e], 1);
    g_tok[r] = i >> 1;
    g_prow[r] = g_probs[i];
}

// weights only: w1 -> g_w1h, w2 -> g_w2h (fp16 round)
#define W4  ((size_t)NEXP * DIM * HID / 4)
__global__ void split_w_kernel(const float* __restrict__ w1,
                               const float* __restrict__ w2) {
    size_t i = (size_t)blockIdx.x * blockDim.x + threadIdx.x;
    if (i >= 2 * W4) return;
    const float* src = (i < W4) ? w1 : w2;
    __half* dst = (i < W4) ? g_w1h : g_w2h;
    size_t k = (i < W4) ? i : i - W4;
    float4 v = ((const float4*)src)[k];
    uint2 ph;
    ph.x = ((uint32_t)__half_as_ushort(__float2half_rn(v.y)) << 16) | __half_as_ushort(__float2half_rn(v.x));
    ph.y = ((uint32_t)__half_as_ushort(__float2half_rn(v.w)) << 16) | __half_as_ushort(__float2half_rn(v.z));
    ((uint2*)dst)[k] = ph;
}

// ---------------- HMMA grouped GEMM (fp16 single-pass, BK=64, 3-stage, 2 CTA/SM) ----
// mode 1: g_hh = fp16(gelu(gather(x) @ W1[e] + b1[e]))
// mode 2: out[t] += p * (g_hh @ W2[e] + b2[e])   (fused combine; exactly 2 adds/elem)
__global__ void __launch_bounds__(256, 2)
moe_gemm_kernel(const float* __restrict__ bias, float* __restrict__ out,
                int K, int Ntot, int mode) {
    extern __shared__ __align__(1024) char smem[];
    int row0 = blockIdx.y * BM;
    if (row0 >= g_off[NEXP]) return;
    int col0 = blockIdx.x * BN;

    int tid = threadIdx.x;
    int wid = tid >> 5, lane = tid & 31;
    int wm = wid & 3, wn = wid >> 2;

    uint32_t sdata = smem_u32(smem) + SM_HDR;
    int* s_tok = (int*)smem;                 // 128 ints
    float* s_prob = (float*)(smem + 512);    // 128 floats

    int e = 0;
#pragma unroll
    for (int i = 0; i < NEXP; i++) if (row0 >= g_off[i + 1]) e++;

    if (tid < BM) {
        s_tok[tid] = g_tok[row0 + tid];
        if (mode == 2) s_prob[tid] = g_prow[row0 + tid];
    }
    __syncthreads();

    const __half* Wh = ((mode == 1) ? g_w1h : g_w2h) + (size_t)e * K * Ntot;

    const int NC = K / BK;

    auto issue = [&](int c) {
        if (c < NC) {
            uint32_t sb = sdata + (c % STAGES) * SSTRIDE;
            int k0 = c * BK;
            // A: 128 rows x 64 fp16 = 1024 chunks of 16B
#pragma unroll
            for (int i = 0; i < 4; i++) {
                int j = i * 256 + tid;
                int ar = j >> 3, ac = (j & 7) * 8;
                uint32_t dA = sb + OFF_A + (uint32_t)(ar * AP + ac) * 2;
                if (mode == 1) {
                    int tk = s_tok[ar];
                    int sz = (tk >= 0) ? 16 : 0;
                    size_t so = (size_t)(tk >= 0 ? tk : 0) * DIM + k0 + ac;
                    cp16z(dA, g_xh + so, sz);
                } else {
                    cp16(dA, g_hh + (size_t)(row0 + ar) * HID + k0 + ac);
                }
            }
            // B: 64 rows x 128 fp16 = 1024 chunks
#pragma unroll
            for (int i = 0; i < 4; i++) {
                int j = i * 256 + tid;
                int br = j >> 4, bc = (j & 15) * 8;
                uint32_t dB = sb + OFF_B + (uint32_t)(br * BP + bc) * 2;
                cp16(dB, Wh + (size_t)(k0 + br) * Ntot + col0 + bc);
            }
        }
        CP_COMMIT();
    };

    float acc[2][8][4];
#pragma unroll
    for (int mf = 0; mf < 2; mf++)
#pragma unroll
        for (int nf = 0; nf < 8; nf++)
#pragma unroll
            for (int q = 0; q < 4; q++) acc[mf][nf][q] = 0.0f;

    issue(0);
    issue(1);

    for (int c = 0; c < NC; c++) {
        CP_WAIT1();
        __syncthreads();
        uint32_t sb = sdata + (c % STAGES) * SSTRIDE;

#pragma unroll
        for (int ks = 0; ks < 4; ks++) {
            uint32_t ah[2][4];
#pragma unroll
            for (int mf = 0; mf < 2; mf++) {
                uint32_t off = (uint32_t)((wm * 32 + mf * 16 + (lane & 15)) * AP
                                          + ks * 16 + (lane >> 4) * 8) * 2;
                ldm_x4(ah[mf], sb + OFF_A + off);
            }
            uint32_t bh[8][2];
#pragma unroll
            for (int ng = 0; ng < 4; ng++) {
                uint32_t off = (uint32_t)((ks * 16 + (lane & 15)) * BP
                                          + wn * 64 + ng * 16 + (lane >> 4) * 8) * 2;
                uint32_t r[4];
                ldm_x4_t(r, sb + OFF_B + off);
                bh[2 * ng][0] = r[0]; bh[2 * ng][1] = r[1];
                bh[2 * ng + 1][0] = r[2]; bh[2 * ng + 1][1] = r[3];
            }
#pragma unroll
            for (int mf = 0; mf < 2; mf++)
#pragma unroll
                for (int nf = 0; nf < 8; nf++)
                    mma_f16(acc[mf][nf], ah[mf], bh[nf]);
        }
        issue(c + 2);
    }

    // ---- epilogue ----
    int grow = lane >> 2;
    int gcol = (lane & 3) * 2;
    if (mode == 1) {
#pragma unroll
        for (int nf = 0; nf < 8; nf++) {
            int col = col0 + wn * 64 + nf * 8 + gcol;
            float b0 = bias[(size_t)e * Ntot + col];
            float b1 = bias[(size_t)e * Ntot + col + 1];
#pragma unroll
            for (int mf = 0; mf < 2; mf++) {
                int rb = row0 + wm * 32 + mf * 16 + grow;
#pragma unroll
                for (int h = 0; h < 2; h++) {
                    int r = rb + h * 8;
                    float v0 = acc[mf][nf][2 * h]     + b0;
                    float v1 = acc[mf][nf][2 * h + 1] + b1;
                    v0 = 0.5f * v0 * (1.0f + erff(v0 * 0.70710678118654752f));
                    v1 = 0.5f * v1 * (1.0f + erff(v1 * 0.70710678118654752f));
                    uint32_t ph = ((uint32_t)__half_as_ushort(__float2half_rn(v1)) << 16)
                                  | __half_as_ushort(__float2half_rn(v0));
                    *(uint32_t*)(g_hh + (size_t)r * HID + col) = ph;
                }
            }
        }
    } else {
        // fused combine: out[t, col] += p * (acc + b2[e, col]); two commutative adds/elem
#pragma unroll
        for (int nf = 0; nf < 8; nf++) {
            int col = col0 + wn * 64 + nf * 8 + gcol;
            float b0 = bias[(size_t)e * Ntot + col];
            float b1 = bias[(size_t)e * Ntot + col + 1];
#pragma unroll
            for (int mf = 0; mf < 2; mf++) {
                int rloc = wm * 32 + mf * 16 + grow;
#pragma unroll
                for (int h = 0; h < 2; h++) {
                    int rl = rloc + h * 8;
                    int t = s_tok[rl];
                    if (t >= 0) {
                        float p = s_prob[rl];
                        float* o = out + (size_t)t * DIM + col;
                        atomicAdd(o,     p * (acc[mf][nf][2 * h]     + b0));
                        atomicAdd(o + 1, p * (acc[mf][nf][2 * h + 1] + b1));
                    }
                }
            }
        }
    }
}

// ---------------- launch ----------------
extern "C" void kernel_launch(void* const* d_in, const int* in_sizes, int n_in,
                              void* d_out, int out_size) {
    const float* x      = (const float*)d_in[0];
    const float* gate_w = (const float*)d_in[1];
    const float* gate_b = (const float*)d_in[2];
    const float* w1     = (const float*)d_in[3];
    const float* b1     = (const float*)d_in[4];
    const float* w2     = (const float*)d_in[5];
    const float* b2     = (const float*)d_in[6];
    float* out = (float*)d_out;

    cudaFuncSetAttribute(moe_gemm_kernel,
                         cudaFuncAttributeMaxDynamicSharedMemorySize, SMEM_TOTAL);

    init_kernel<<<2048, 256>>>(out);
    gate_kernel<<<(T_TOK * 32) / 256, 256>>>(x, gate_w, gate_b);
    finalize_gate_kernel<<<1, 32>>>(out, (long long)out_size);
    scatter_kernel<<<(T_TOK * TOPK + 255) / 256, 256>>>();
    split_w_kernel<<<(unsigned)((2 * W4 + 255) / 256), 256>>>(w1, w2);
    // GEMM1: K=1024, N=4096
    {
        dim3 grid(HID / BN, ROWS_MAX / BM);
        moe_gemm_kernel<<<grid, 256, SMEM_TOTAL>>>(b1, out, DIM, HID, 1);
    }
    // GEMM2 (+fused combine): K=4096, N=1024
    {
        dim3 grid(DIM / BN, ROWS_MAX / BM);
        moe_gemm_kernel<<<grid, 256, SMEM_TOTAL>>>(b2, out, HID, DIM, 2);
    }
}